// round 1
// baseline (speedup 1.0000x reference)
#include <cuda_runtime.h>

// Problem constants
#define BT    8192      // B*T queries
#define KCB   8192      // codewords per codebook
#define DDIM  128
#define TLEN  1024
#define CCH   256
#define NQ    2097152   // B*C*T quantized elements
#define NIDX  16384     // B*NCB*T indices

// Scratch (device globals; no allocation allowed)
__device__ float  g_c2[2 * KCB];
__device__ float  g_x2[2 * BT];
__device__ int    g_idx[2 * BT];
__device__ double g_sse;

// ---------------------------------------------------------------------------
// packed fp32x2 helpers (Blackwell FFMA2 — only reachable via PTX)
// ---------------------------------------------------------------------------
__device__ __forceinline__ unsigned long long dup2(float x) {
    unsigned long long r;
    asm("mov.b64 %0, {%1, %1};" : "=l"(r) : "f"(x));
    return r;
}
__device__ __forceinline__ void ffma2(unsigned long long& acc,
                                      unsigned long long a,
                                      unsigned long long b) {
    asm("fma.rn.f32x2 %0, %1, %2, %0;" : "+l"(acc) : "l"(a), "l"(b));
}
__device__ __forceinline__ void unpack2(unsigned long long p, float& lo, float& hi) {
    asm("mov.b64 {%0, %1}, %2;" : "=f"(lo), "=f"(hi) : "l"(p));
}

// ---------------------------------------------------------------------------
// init
// ---------------------------------------------------------------------------
__global__ void zero_kernel() { g_sse = 0.0; }

// ---------------------------------------------------------------------------
// c2[n*K + k] = sum_d codebooks[n][k][d]^2   (one warp per row)
// ---------------------------------------------------------------------------
__global__ void c2_kernel(const float* __restrict__ cb) {
    int row  = blockIdx.x * 8 + (threadIdx.x >> 5);
    int lane = threadIdx.x & 31;
    float4 v = *reinterpret_cast<const float4*>(cb + (size_t)row * DDIM + lane * 4);
    float s = v.x * v.x + v.y * v.y + v.z * v.z + v.w * v.w;
    #pragma unroll
    for (int o = 16; o; o >>= 1) s += __shfl_down_sync(0xFFFFFFFFu, s, o);
    if (lane == 0) g_c2[row] = s;
}

// ---------------------------------------------------------------------------
// x2[n*BT + bt] = sum_d x[b][n*128+d][t]^2  (coalesced along t)
// blockIdx: n*256 + b*32 + ttile ; block 256 threads
// ---------------------------------------------------------------------------
__global__ void x2_kernel(const float* __restrict__ x) {
    int bi = blockIdx.x;
    int n  = bi >> 8;
    int b  = (bi >> 5) & 7;
    int t0 = (bi & 31) * 32;
    int tt = threadIdx.x & 31;
    int g  = threadIdx.x >> 5;

    const float* xp = x + ((size_t)b * CCH + (size_t)n * DDIM) * TLEN + t0 + tt;
    float s = 0.f;
    #pragma unroll
    for (int j = 0; j < 16; ++j) {
        float v = xp[(size_t)(g * 16 + j) * TLEN];
        s += v * v;
    }
    __shared__ float sm[8][33];
    sm[g][tt] = s;
    __syncthreads();
    if (threadIdx.x < 32) {
        float tot = 0.f;
        #pragma unroll
        for (int j = 0; j < 8; ++j) tot += sm[j][threadIdx.x];
        g_x2[n * BT + b * TLEN + t0 + threadIdx.x] = tot;
    }
}

// ---------------------------------------------------------------------------
// Fused GEMM + argmin. grid (64 qtiles, 2 codebooks), block 256.
// Block tile: 128 queries x 128 codewords per k-tile, 64 k-tiles.
// smem: qs[128][132], cs[128][132] (d-major), + 16KB reduce space.
// Thread (tx=tid&15, ty=tid>>4): q rows {4ty..4ty+3, 64+4ty..+3},
//                                k cols {4tx..4tx+3, 64+4tx..+3}.
// ---------------------------------------------------------------------------
#define ROWS  132
#define SMEM_FLOATS (16896 * 2 + 2048 * 2)   // 37888 floats = 151552 B

__global__ void __launch_bounds__(256, 1)
vq_kernel(const float* __restrict__ x, const float* __restrict__ cb,
          float* __restrict__ out) {
    extern __shared__ float sm[];
    float* qs   = sm;                 // 128*132
    float* cs   = sm + 16896;         // 128*132
    float* redv = sm + 33792;         // 128*16
    int*   redi = (int*)(sm + 35840); // 128*16

    const int tid = threadIdx.x;
    const int tx  = tid & 15;
    const int ty  = tid >> 4;
    const int n   = blockIdx.y;
    const int qbase = blockIdx.x * 128;
    const int b   = qbase >> 10;
    const int t0  = qbase & 1023;

    const float* xq  = x  + ((size_t)b * CCH + (size_t)n * DDIM) * TLEN + t0;
    const float* cbn = cb + (size_t)n * KCB * DDIM;

    // ---- load query tile qs[d][t] (coalesced along t) ----
    #pragma unroll
    for (int l = 0; l < 16; ++l) {
        int lin = l * 256 + tid;
        int d   = lin >> 5;
        int t4  = lin & 31;
        float4 v = *reinterpret_cast<const float4*>(xq + (size_t)d * TLEN + t4 * 4);
        *reinterpret_cast<float4*>(qs + d * ROWS + t4 * 4) = v;
    }

    // ---- per-thread x2 values (JAX grid replication uses x2) ----
    float x2r[8];
    #pragma unroll
    for (int i = 0; i < 8; ++i) {
        int qr = (i < 4) ? (4 * ty + i) : (64 + 4 * ty + (i - 4));
        x2r[i] = g_x2[n * BT + qbase + qr];
    }

    float bestv[8];
    int   bestk[8];
    #pragma unroll
    for (int i = 0; i < 8; ++i) { bestv[i] = 3.4e38f; bestk[i] = 0; }

    for (int tile = 0; tile < 64; ++tile) {
        const int kbase = tile * 128;
        __syncthreads();
        // ---- load codebook tile transposed: cs[d][kk] = cb[kbase+kk][d] ----
        #pragma unroll
        for (int l = 0; l < 16; ++l) {
            int lin = l * 256 + tid;
            int kk  = (lin & 7) | (((lin >> 8) & 15) << 3);
            int d4  = ((lin >> 3) & 3) | (((lin >> 5) & 7) << 2);
            float4 v = *reinterpret_cast<const float4*>(
                cbn + (size_t)(kbase + kk) * DDIM + d4 * 4);
            cs[(d4 * 4 + 0) * ROWS + kk] = v.x;
            cs[(d4 * 4 + 1) * ROWS + kk] = v.y;
            cs[(d4 * 4 + 2) * ROWS + kk] = v.z;
            cs[(d4 * 4 + 3) * ROWS + kk] = v.w;
        }
        __syncthreads();

        // ---- FFMA2 main loop: acc[i][jp] = packed xc pairs ----
        unsigned long long acc[8][4];
        #pragma unroll
        for (int i = 0; i < 8; ++i)
            #pragma unroll
            for (int j = 0; j < 4; ++j) acc[i][j] = 0ull;

        #pragma unroll 4
        for (int d = 0; d < 128; ++d) {
            const float4 a0 = *reinterpret_cast<const float4*>(qs + d * ROWS + 4 * ty);
            const float4 a1 = *reinterpret_cast<const float4*>(qs + d * ROWS + 64 + 4 * ty);
            const ulonglong2 b0 = *reinterpret_cast<const ulonglong2*>(cs + d * ROWS + 4 * tx);
            const ulonglong2 b1 = *reinterpret_cast<const ulonglong2*>(cs + d * ROWS + 64 + 4 * tx);
            unsigned long long A[8];
            A[0] = dup2(a0.x); A[1] = dup2(a0.y); A[2] = dup2(a0.z); A[3] = dup2(a0.w);
            A[4] = dup2(a1.x); A[5] = dup2(a1.y); A[6] = dup2(a1.z); A[7] = dup2(a1.w);
            #pragma unroll
            for (int i = 0; i < 8; ++i) {
                ffma2(acc[i][0], A[i], b0.x);
                ffma2(acc[i][1], A[i], b0.y);
                ffma2(acc[i][2], A[i], b1.x);
                ffma2(acc[i][3], A[i], b1.y);
            }
        }

        // ---- epilogue: d2 with JAX's exact fp32 rounding, running argmin ----
        float c2v[8];
        #pragma unroll
        for (int j = 0; j < 8; ++j) {
            int kc = (j < 4) ? (4 * tx + j) : (64 + 4 * tx + (j - 4));
            c2v[j] = __ldg(&g_c2[n * KCB + kbase + kc]);
        }
        #pragma unroll
        for (int i = 0; i < 8; ++i) {
            #pragma unroll
            for (int jp = 0; jp < 4; ++jp) {
                float lo, hi;
                unpack2(acc[i][jp], lo, hi);
                int j0 = jp * 2;
                int k0 = kbase + ((j0 < 4) ? (4 * tx + j0) : (64 + 4 * tx + (j0 - 4)));
                // JAX: d2 = (x2 - (2*xc)) + c2, each step rounded in fp32
                float d2a = __fadd_rn(__fsub_rn(x2r[i], __fmul_rn(2.0f, lo)), c2v[j0]);
                if (d2a < bestv[i]) { bestv[i] = d2a; bestk[i] = k0; }
                float d2b = __fadd_rn(__fsub_rn(x2r[i], __fmul_rn(2.0f, hi)), c2v[j0 + 1]);
                if (d2b < bestv[i]) { bestv[i] = d2b; bestk[i] = k0 + 1; }
            }
        }
    }

    // ---- cross-thread argmin reduce (16 tx lanes per query row) ----
    __syncthreads();
    #pragma unroll
    for (int i = 0; i < 8; ++i) {
        int qr = (i < 4) ? (4 * ty + i) : (64 + 4 * ty + (i - 4));
        redv[qr * 16 + tx] = bestv[i];
        redi[qr * 16 + tx] = bestk[i];
    }
    __syncthreads();
    if (tid < 128) {
        float bv = 3.4e38f;
        int   bk = 1 << 30;
        for (int j = 0; j < 16; ++j) {
            float v = redv[tid * 16 + j];
            int   k = redi[tid * 16 + j];
            if (v < bv || (v == bv && k < bk)) { bv = v; bk = k; }
        }
        int bt = qbase + tid;
        int bb = bt >> 10;
        int t  = bt & 1023;
        out[NQ + ((size_t)bb * 2 + n) * TLEN + t] = (float)bk;  // indices (B,NCB,T)
        g_idx[n * BT + bt] = bk;
    }
}

// ---------------------------------------------------------------------------
// Gather quantized output + commit-loss SSE. block = one (n, bt), 128 threads.
// ---------------------------------------------------------------------------
__global__ void gather_kernel(const float* __restrict__ x,
                              const float* __restrict__ cb,
                              float* __restrict__ out) {
    int bi = blockIdx.x;              // n*8192 + bt
    int n  = bi >> 13;
    int bt = bi & 8191;
    int b  = bt >> 10;
    int t  = bt & 1023;
    int k  = g_idx[n * BT + bt];
    int i  = threadIdx.x;

    float q = cb[(size_t)n * KCB * DDIM + (size_t)k * DDIM + i];
    size_t oidx = ((size_t)b * CCH + (size_t)n * DDIM + i) * TLEN + t;
    out[oidx] = q;

    float d = x[oidx] - q;
    float s = d * d;
    #pragma unroll
    for (int o = 16; o; o >>= 1) s += __shfl_down_sync(0xFFFFFFFFu, s, o);
    __shared__ float sm4[4];
    if ((i & 31) == 0) sm4[i >> 5] = s;
    __syncthreads();
    if (i == 0) atomicAdd(&g_sse, (double)(sm4[0] + sm4[1] + sm4[2] + sm4[3]));
}

__global__ void fin_kernel(float* __restrict__ out) {
    out[NQ + NIDX] = (float)(0.25 * g_sse / (double)((long long)BT * DDIM));
}

// ---------------------------------------------------------------------------
extern "C" void kernel_launch(void* const* d_in, const int* in_sizes, int n_in,
                              void* d_out, int out_size) {
    const float* x  = (const float*)d_in[0];
    const float* cb = (const float*)d_in[1];
    float* out = (float*)d_out;

    cudaFuncSetAttribute(vq_kernel,
                         cudaFuncAttributeMaxDynamicSharedMemorySize,
                         SMEM_FLOATS * 4);

    zero_kernel<<<1, 1>>>();
    c2_kernel<<<2048, 256>>>(cb);
    x2_kernel<<<512, 256>>>(x);
    dim3 g(64, 2);
    vq_kernel<<<g, 256, SMEM_FLOATS * 4>>>(x, cb, out);
    gather_kernel<<<16384, 128>>>(x, cb, out);
    fin_kernel<<<1, 1>>>(out);
}